// round 3
// baseline (speedup 1.0000x reference)
#include <cuda_runtime.h>
#include <math.h>

#define B_ 32
#define T_ 63
#define NB 64
#define H_ 64
#define KIN 4096
#define BT (B_*T_)            // 2016
#define MROWS (BT*NB)         // 129024
#define NG 9
#define NCOLS (NG*H_)         // 576
#define KST 256

// ---- scratch (static device allocations; no runtime allocs) ----
__device__ float d_h[2][MROWS*H_];          // 2 x 33 MB
__device__ float d_c[2][MROWS*H_];          // 2 x 33 MB
__device__ float d_cst[(size_t)MROWS*NCOLS]; // 297 MB: folded constants per (row, gate, h)
__device__ float d_pre[(size_t)MROWS*NCOLS]; // 297 MB: gate pre-activations
__device__ float d_x[(size_t)MROWS*KST];     // 132 MB: gathered step input
__device__ float d_gt[B_*NB*H_];             // mean over T
__device__ float d_gs[BT*H_];                // mean over N
__device__ float d_gtt[NG*B_*NB*H_];         // g_t @ Zt
__device__ float d_gst[NG*BT*H_];            // g_s @ Zs[idx]
__device__ float d_wc[KST*NCOLS];            // [Wt;Ws] concatenated, (256 x 576)

__constant__ int c_zs[NG] = {0,1,1,3,4,5,6,7,8};

__device__ __forceinline__ float sigm(float x) { return 1.0f / (1.0f + expf(-x)); }

// ---------------- build Wcat (256 x 576): rows 0..191 = Wt[g], 192..255 = Ws[g] ----
__global__ void k_wcat(const float* __restrict__ Wt, const float* __restrict__ Ws) {
    int i = blockIdx.x * 256 + threadIdx.x;      // KST*NCOLS = 147456
    if (i >= KST * NCOLS) return;
    int k = i / NCOLS;
    int c = i % NCOLS;
    int g = c >> 6, h = c & 63;
    float v = (k < 192) ? Wt[(g * 192 + k) * 64 + h]
                        : Ws[(g * 64 + (k - 192)) * 64 + h];
    d_wc[i] = v;
}

// ---------------- input projection: h0 = enc @ Win + bias ----------------
// C[2016,4096] ; 128x128 tile, K-chunk 16, 256 threads, 8x8 per thread
__global__ __launch_bounds__(256) void k_gemm_in(const float* __restrict__ A,
                                                 const float* __restrict__ W,
                                                 const float* __restrict__ bias) {
    __shared__ float As[16][132];   // transposed A tile (pad to dodge store conflicts)
    __shared__ float Bs[16][128];
    const int tid = threadIdx.x;
    const int tx = tid & 15, ty = tid >> 4;
    const int row0 = blockIdx.y * 128, col0 = blockIdx.x * 128;
    const int ar = tid >> 2, ac = (tid & 3) * 4;
    const int br = tid >> 5, bc = (tid & 31) * 4;
    float acc[8][8];
    #pragma unroll
    for (int i = 0; i < 8; i++)
        #pragma unroll
        for (int j = 0; j < 8; j++) acc[i][j] = 0.f;

    for (int k0 = 0; k0 < KIN; k0 += 16) {
        float4 a0 = make_float4(0.f,0.f,0.f,0.f), a1 = a0;
        if (row0 + ar < BT)
            a0 = *(const float4*)&A[(size_t)(row0 + ar) * KIN + k0 + ac];
        if (row0 + ar + 64 < BT)
            a1 = *(const float4*)&A[(size_t)(row0 + ar + 64) * KIN + k0 + ac];
        float4 b0 = *(const float4*)&W[(size_t)(k0 + br) * KIN + col0 + bc];
        float4 b1 = *(const float4*)&W[(size_t)(k0 + br + 8) * KIN + col0 + bc];
        __syncthreads();
        As[ac + 0][ar] = a0.x; As[ac + 1][ar] = a0.y;
        As[ac + 2][ar] = a0.z; As[ac + 3][ar] = a0.w;
        As[ac + 0][ar + 64] = a1.x; As[ac + 1][ar + 64] = a1.y;
        As[ac + 2][ar + 64] = a1.z; As[ac + 3][ar + 64] = a1.w;
        *(float4*)&Bs[br][bc]     = b0;
        *(float4*)&Bs[br + 8][bc] = b1;
        __syncthreads();
        #pragma unroll
        for (int kk = 0; kk < 16; kk++) {
            float4 x0 = *(const float4*)&As[kk][ty * 8];
            float4 x1 = *(const float4*)&As[kk][ty * 8 + 4];
            float4 y0 = *(const float4*)&Bs[kk][tx * 8];
            float4 y1 = *(const float4*)&Bs[kk][tx * 8 + 4];
            float a[8] = {x0.x, x0.y, x0.z, x0.w, x1.x, x1.y, x1.z, x1.w};
            float w[8] = {y0.x, y0.y, y0.z, y0.w, y1.x, y1.y, y1.z, y1.w};
            #pragma unroll
            for (int i = 0; i < 8; i++)
                #pragma unroll
                for (int j = 0; j < 8; j++)
                    acc[i][j] = fmaf(a[i], w[j], acc[i][j]);
        }
    }
    #pragma unroll
    for (int i = 0; i < 8; i++) {
        int row = row0 + ty * 8 + i;
        if (row >= BT) break;
        #pragma unroll
        for (int j = 0; j < 8; j += 4) {
            int col = col0 + tx * 8 + j;
            float4 v;
            v.x = acc[i][j + 0] + bias[col + 0];
            v.y = acc[i][j + 1] + bias[col + 1];
            v.z = acc[i][j + 2] + bias[col + 2];
            v.w = acc[i][j + 3] + bias[col + 3];
            *(float4*)&d_h[0][(size_t)row * KIN + col] = v;
            *(float4*)&d_c[0][(size_t)row * KIN + col] = v;
        }
    }
}

// ---------------- means ----------------
__global__ void k_mean_t() {   // g_t[b,n,h] = mean_t h0
    int i = blockIdx.x * 256 + threadIdx.x;   // B*NB*H = 131072
    int hh = i & 63, n = (i >> 6) & 63, b = i >> 12;
    const float* p = d_h[0] + ((size_t)(b * T_) * NB + n) * H_ + hh;
    float s = 0.f;
    for (int t = 0; t < T_; t++) s += p[(size_t)t * NB * H_];
    d_gt[i] = s * (1.0f / T_);
}
__global__ void k_mean_n() {   // g_s[b,t,h] = mean_n h0
    int i = blockIdx.x * 256 + threadIdx.x;   // BT*H = 129024
    int hh = i & 63, bt = i >> 6;
    const float* p = d_h[0] + (size_t)bt * NB * H_ + hh;
    float s = 0.f;
    for (int n = 0; n < NB; n++) s += p[n * H_];
    d_gs[i] = s * (1.0f / NB);
}

// ---------------- small 9-gate gemms: out[g,m,:] = X[m,:] @ W[g or zs_idx[g]] ----
__global__ __launch_bounds__(256) void k_ninegemm(int which, const float* __restrict__ Wbase) {
    const int g = blockIdx.x;
    const int m0 = blockIdx.y * 64;
    const float* X = which ? d_gs : d_gt;
    float* out = which ? d_gst : d_gtt;
    const int M = which ? BT : (B_ * NB);
    const float* Wg = Wbase + (size_t)(which ? c_zs[g] : g) * 4096;

    __shared__ float XT[64][68];
    __shared__ float Wsm[64][68];
    const int tid = threadIdx.x;
    for (int i = tid; i < 4096; i += 256) {
        int r = i >> 6, k = i & 63;
        XT[k][r] = (m0 + r < M) ? X[(size_t)(m0 + r) * 64 + k] : 0.f;
        Wsm[r][k] = Wg[i];          // Wsm[in][out]
    }
    __syncthreads();
    const int tx = tid & 15, ty = tid >> 4;
    float acc[4][4];
    #pragma unroll
    for (int i = 0; i < 4; i++)
        #pragma unroll
        for (int j = 0; j < 4; j++) acc[i][j] = 0.f;
    #pragma unroll 16
    for (int kk = 0; kk < 64; kk++) {
        float4 a = *(const float4*)&XT[kk][ty * 4];
        float4 w = *(const float4*)&Wsm[kk][tx * 4];
        float av[4] = {a.x, a.y, a.z, a.w};
        float wv[4] = {w.x, w.y, w.z, w.w};
        #pragma unroll
        for (int i = 0; i < 4; i++)
            #pragma unroll
            for (int j = 0; j < 4; j++)
                acc[i][j] = fmaf(av[i], wv[j], acc[i][j]);
    }
    #pragma unroll
    for (int i = 0; i < 4; i++) {
        int row = m0 + ty * 4 + i;
        if (row >= M) break;
        float4 v = make_float4(acc[i][0], acc[i][1], acc[i][2], acc[i][3]);
        *(float4*)&out[((size_t)g * M + row) * 64 + tx * 4] = v;
    }
}

// ---------------- CONST[r, g*64+h] = h0[r,:]@U[g] + gtt + gst + bias ----------------
__global__ __launch_bounds__(256) void k_const(const float* __restrict__ U,
                                               const float* __restrict__ bb) {
    const int g = blockIdx.x;
    const int bt = blockIdx.y;          // 0..2015 -> rows bt*64..+63 share (b,t)
    const int b = bt / T_;
    __shared__ float XT[64][68];
    __shared__ float Us[64][68];
    const int tid = threadIdx.x;
    const int base = bt * 64;
    for (int i = tid; i < 4096; i += 256) {
        int n = i >> 6, k = i & 63;
        XT[k][n] = d_h[0][(size_t)(base + n) * 64 + k];
        Us[n][k] = U[(size_t)g * 4096 + i];   // Us[in][out]
    }
    __syncthreads();
    const int tx = tid & 15, ty = tid >> 4;
    float acc[4][4];
    #pragma unroll
    for (int i = 0; i < 4; i++)
        #pragma unroll
        for (int j = 0; j < 4; j++) acc[i][j] = 0.f;
    #pragma unroll 16
    for (int kk = 0; kk < 64; kk++) {
        float4 a = *(const float4*)&XT[kk][ty * 4];
        float4 w = *(const float4*)&Us[kk][tx * 4];
        float av[4] = {a.x, a.y, a.z, a.w};
        float wv[4] = {w.x, w.y, w.z, w.w};
        #pragma unroll
        for (int i = 0; i < 4; i++)
            #pragma unroll
            for (int j = 0; j < 4; j++)
                acc[i][j] = fmaf(av[i], wv[j], acc[i][j]);
    }
    #pragma unroll
    for (int i = 0; i < 4; i++) {
        int n = ty * 4 + i;
        int row = base + n;
        float4 agt = *(const float4*)&d_gtt[((size_t)g * B_ * NB + (b * NB + n)) * H_ + tx * 4];
        float4 ags = *(const float4*)&d_gst[((size_t)g * BT + bt) * H_ + tx * 4];
        float4 abb = *(const float4*)&bb[(size_t)g * H_ * H_ + n * H_ + tx * 4];
        float4 v;
        v.x = acc[i][0] + agt.x + ags.x + abb.x;
        v.y = acc[i][1] + agt.y + ags.y + abb.y;
        v.z = acc[i][2] + agt.z + ags.z + abb.z;
        v.w = acc[i][3] + agt.w + ags.w + abb.w;
        *(float4*)&d_cst[(size_t)row * NCOLS + g * 64 + tx * 4] = v;
    }
}

// ---------------- gather xin = [h(t-1), h, h(t+1), h(n-1)] ----------------
__global__ void k_gather(int cur) {
    int i = blockIdx.x * 256 + threadIdx.x;   // MROWS * 64 float4s
    int r = i >> 6;
    int c4 = (i & 63) << 2;                   // 0..252
    int n = r & 63, bt = r >> 6, t = bt % T_;
    int sec = c4 >> 6, hh = c4 & 63;
    const float* h = d_h[cur];
    float4 v = make_float4(0.f, 0.f, 0.f, 0.f);
    if (sec == 1) {
        v = *(const float4*)&h[(size_t)r * 64 + hh];
    } else if (sec == 0) {
        if (t > 0) v = *(const float4*)&h[(size_t)(r - 64) * 64 + hh];
    } else if (sec == 2) {
        if (t < T_ - 1) v = *(const float4*)&h[(size_t)(r + 64) * 64 + hh];
    } else {
        if (n > 0) v = *(const float4*)&h[(size_t)(r - 1) * 64 + hh];
    }
    *(float4*)&d_x[(size_t)r * KST + c4] = v;
}

// ---------------- step GEMM: PRE = CONST + Xin @ Wcat ----------------
// grid(9 gates, 1008 row-tiles); tile 128x64, K=256
__global__ __launch_bounds__(256) void k_stepgemm() {
    const int g = blockIdx.x;
    const int row0 = blockIdx.y * 128;
    const int gcol = g * 64;
    __shared__ float As[16][132];
    __shared__ float Bs[16][64];
    const int tid = threadIdx.x;
    const int tx = tid & 15, ty = tid >> 4;
    const int ar = tid >> 2, ac = (tid & 3) * 4;
    const int br = tid >> 4, bc = (tid & 15) * 4;
    float acc[8][4];
    #pragma unroll
    for (int i = 0; i < 8; i++)
        #pragma unroll
        for (int j = 0; j < 4; j++) acc[i][j] = 0.f;

    for (int k0 = 0; k0 < KST; k0 += 16) {
        float4 a0 = *(const float4*)&d_x[(size_t)(row0 + ar) * KST + k0 + ac];
        float4 a1 = *(const float4*)&d_x[(size_t)(row0 + ar + 64) * KST + k0 + ac];
        float4 b0 = *(const float4*)&d_wc[(size_t)(k0 + br) * NCOLS + gcol + bc];
        __syncthreads();
        As[ac + 0][ar] = a0.x; As[ac + 1][ar] = a0.y;
        As[ac + 2][ar] = a0.z; As[ac + 3][ar] = a0.w;
        As[ac + 0][ar + 64] = a1.x; As[ac + 1][ar + 64] = a1.y;
        As[ac + 2][ar + 64] = a1.z; As[ac + 3][ar + 64] = a1.w;
        *(float4*)&Bs[br][bc] = b0;
        __syncthreads();
        #pragma unroll
        for (int kk = 0; kk < 16; kk++) {
            float4 x0 = *(const float4*)&As[kk][ty * 8];
            float4 x1 = *(const float4*)&As[kk][ty * 8 + 4];
            float4 y  = *(const float4*)&Bs[kk][tx * 4];
            float a[8] = {x0.x, x0.y, x0.z, x0.w, x1.x, x1.y, x1.z, x1.w};
            float w[4] = {y.x, y.y, y.z, y.w};
            #pragma unroll
            for (int i = 0; i < 8; i++)
                #pragma unroll
                for (int j = 0; j < 4; j++)
                    acc[i][j] = fmaf(a[i], w[j], acc[i][j]);
        }
    }
    #pragma unroll
    for (int i = 0; i < 8; i++) {
        int row = row0 + ty * 8 + i;
        size_t o = (size_t)row * NCOLS + gcol + tx * 4;
        float4 cc = *(const float4*)&d_cst[o];
        float4 v = make_float4(acc[i][0] + cc.x, acc[i][1] + cc.y,
                               acc[i][2] + cc.z, acc[i][3] + cc.w);
        *(float4*)&d_pre[o] = v;
    }
}

// ---------------- cell update ----------------
__global__ void k_cell(int cur, float* __restrict__ hout) {
    int i = blockIdx.x * 256 + threadIdx.x;   // MROWS*H = 8257536
    int hh = i & 63;
    int r = i >> 6;
    int n = r & 63, bt = r >> 6;
    int t = bt % T_, b = bt / T_;
    const float* p = d_pre + (size_t)r * NCOLS + hh;
    float i_n  = sigm(p[0]);
    float f_lt = sigm(p[64]);
    float f_ft = sigm(p[128]);
    float f_rt = sigm(p[192]);
    float f_s  = sigm(p[256]);
    float f_gt = sigm(p[320]);
    float f_gs = sigm(p[384]);
    float o_n  = sigm(p[448]);
    float c_n  = tanhf(p[512]);
    const float* c_old = d_c[cur];
    float cc  = c_old[i];
    float ctb = (t > 0)      ? c_old[i - 4096] : 0.f;   // t-1 -> row r-64
    float cta = (t < T_ - 1) ? c_old[i + 4096] : 0.f;   // t+1
    float csb = (n > 0)      ? c_old[i - 64]   : 0.f;   // n-1
    float cgt = d_gt[(b * NB + n) * H_ + hh];
    float cgs = d_gs[bt * H_ + hh];
    float c = f_lt * ctb + f_ft * cc + f_rt * cta + f_s * csb
            + f_gt * cgt + f_gs * cgs + c_n * i_n;
    d_c[cur ^ 1][i] = c;
    float hv = o_n * tanhf(c);
    if (hout) hout[i] = hv;
    else      d_h[cur ^ 1][i] = hv;
}

extern "C" void kernel_launch(void* const* d_in, const int* in_sizes, int n_in,
                              void* d_out, int out_size) {
    const float* enc = (const float*)d_in[0];
    // d_in[1] = decoder_inputs: unused by the reference
    const float* Win = (const float*)d_in[2];
    const float* bin = (const float*)d_in[3];
    const float* U   = (const float*)d_in[4];
    const float* Wt  = (const float*)d_in[5];
    const float* Ws  = (const float*)d_in[6];
    const float* Zt  = (const float*)d_in[7];
    const float* Zs  = (const float*)d_in[8];
    const float* bb  = (const float*)d_in[9];
    float* out = (float*)d_out;

    k_wcat<<<(KST * NCOLS + 255) / 256, 256>>>(Wt, Ws);
    k_gemm_in<<<dim3(32, 16), 256>>>(enc, Win, bin);
    k_mean_t<<<(B_ * NB * H_) / 256, 256>>>();
    k_mean_n<<<(BT * H_) / 256, 256>>>();
    k_ninegemm<<<dim3(NG, 32), 256>>>(0, Zt);   // gtt: M=2048
    k_ninegemm<<<dim3(NG, 32), 256>>>(1, Zs);   // gst: M=2016
    k_const<<<dim3(NG, BT), 256>>>(U, bb);

    for (int s = 0; s < 3; s++) {
        int cur = s & 1;
        k_gather<<<(MROWS * 64) / 256, 256>>>(cur);
        k_stepgemm<<<dim3(NG, MROWS / 128), 256>>>();
        k_cell<<<(MROWS * H_) / 256, 256>>>(cur, (s == 2) ? out : nullptr);
    }
}

// round 4
// speedup vs baseline: 1.5219x; 1.5219x over previous
#include <cuda_runtime.h>
#include <math.h>

#define B_ 32
#define T_ 63
#define NB 64
#define H_ 64
#define KIN 4096
#define BT (B_*T_)            // 2016
#define MROWS (BT*NB)         // 129024
#define NG 9
#define NCOLS (NG*H_)         // 576
#define KST 256

// ---- scratch (static device allocations; no runtime allocs) ----
__device__ float d_h[2][MROWS*H_];          // 2 x 33 MB
__device__ float d_c[2][MROWS*H_];          // 2 x 33 MB
__device__ float d_cst[(size_t)MROWS*NCOLS]; // 297 MB: folded constants per (row, gate, h)
__device__ float d_pre[(size_t)MROWS*NCOLS]; // 297 MB: gate pre-activations
__device__ float d_x[(size_t)MROWS*KST];     // 132 MB: gathered step input
__device__ float d_gt[B_*NB*H_];             // mean over T
__device__ float d_gs[BT*H_];                // mean over N
__device__ float d_gtt[NG*B_*NB*H_];         // g_t @ Zt
__device__ float d_gst[NG*BT*H_];            // g_s @ Zs[idx]
__device__ float d_wc[KST*NCOLS];            // [Wt;Ws] concatenated, (256 x 576)

__constant__ int c_zs[NG] = {0,1,1,3,4,5,6,7,8};

__device__ __forceinline__ float sigm(float x) { return 1.0f / (1.0f + expf(-x)); }

// ---------------- build Wcat (256 x 576): rows 0..191 = Wt[g], 192..255 = Ws[g] ----
__global__ void k_wcat(const float* __restrict__ Wt, const float* __restrict__ Ws) {
    int i = blockIdx.x * 256 + threadIdx.x;      // KST*NCOLS = 147456
    if (i >= KST * NCOLS) return;
    int k = i / NCOLS;
    int c = i % NCOLS;
    int g = c >> 6, h = c & 63;
    float v = (k < 192) ? Wt[(g * 192 + k) * 64 + h]
                        : Ws[(g * 64 + (k - 192)) * 64 + h];
    d_wc[i] = v;
}

// ---------------- input projection: h0 = enc @ Win + bias ----------------
// C[2016,4096] ; 128x128 tile, K-chunk 16, 256 threads, 8x8 per thread
__global__ __launch_bounds__(256) void k_gemm_in(const float* __restrict__ A,
                                                 const float* __restrict__ W,
                                                 const float* __restrict__ bias) {
    __shared__ float As[16][132];   // transposed A tile (pad to dodge store conflicts)
    __shared__ float Bs[16][128];
    const int tid = threadIdx.x;
    const int tx = tid & 15, ty = tid >> 4;
    const int row0 = blockIdx.y * 128, col0 = blockIdx.x * 128;
    const int ar = tid >> 2, ac = (tid & 3) * 4;
    const int br = tid >> 5, bc = (tid & 31) * 4;
    float acc[8][8];
    #pragma unroll
    for (int i = 0; i < 8; i++)
        #pragma unroll
        for (int j = 0; j < 8; j++) acc[i][j] = 0.f;

    for (int k0 = 0; k0 < KIN; k0 += 16) {
        float4 a0 = make_float4(0.f,0.f,0.f,0.f), a1 = a0;
        if (row0 + ar < BT)
            a0 = *(const float4*)&A[(size_t)(row0 + ar) * KIN + k0 + ac];
        if (row0 + ar + 64 < BT)
            a1 = *(const float4*)&A[(size_t)(row0 + ar + 64) * KIN + k0 + ac];
        float4 b0 = *(const float4*)&W[(size_t)(k0 + br) * KIN + col0 + bc];
        float4 b1 = *(const float4*)&W[(size_t)(k0 + br + 8) * KIN + col0 + bc];
        __syncthreads();
        As[ac + 0][ar] = a0.x; As[ac + 1][ar] = a0.y;
        As[ac + 2][ar] = a0.z; As[ac + 3][ar] = a0.w;
        As[ac + 0][ar + 64] = a1.x; As[ac + 1][ar + 64] = a1.y;
        As[ac + 2][ar + 64] = a1.z; As[ac + 3][ar + 64] = a1.w;
        *(float4*)&Bs[br][bc]     = b0;
        *(float4*)&Bs[br + 8][bc] = b1;
        __syncthreads();
        #pragma unroll
        for (int kk = 0; kk < 16; kk++) {
            float4 x0 = *(const float4*)&As[kk][ty * 8];
            float4 x1 = *(const float4*)&As[kk][ty * 8 + 4];
            float4 y0 = *(const float4*)&Bs[kk][tx * 8];
            float4 y1 = *(const float4*)&Bs[kk][tx * 8 + 4];
            float a[8] = {x0.x, x0.y, x0.z, x0.w, x1.x, x1.y, x1.z, x1.w};
            float w[8] = {y0.x, y0.y, y0.z, y0.w, y1.x, y1.y, y1.z, y1.w};
            #pragma unroll
            for (int i = 0; i < 8; i++)
                #pragma unroll
                for (int j = 0; j < 8; j++)
                    acc[i][j] = fmaf(a[i], w[j], acc[i][j]);
        }
    }
    #pragma unroll
    for (int i = 0; i < 8; i++) {
        int row = row0 + ty * 8 + i;
        if (row >= BT) break;
        #pragma unroll
        for (int j = 0; j < 8; j += 4) {
            int col = col0 + tx * 8 + j;
            float4 v;
            v.x = acc[i][j + 0] + bias[col + 0];
            v.y = acc[i][j + 1] + bias[col + 1];
            v.z = acc[i][j + 2] + bias[col + 2];
            v.w = acc[i][j + 3] + bias[col + 3];
            *(float4*)&d_h[0][(size_t)row * KIN + col] = v;
            *(float4*)&d_c[0][(size_t)row * KIN + col] = v;
        }
    }
}

// ---------------- means ----------------
__global__ void k_mean_t() {   // g_t[b,n,h] = mean_t h0
    int i = blockIdx.x * 256 + threadIdx.x;   // B*NB*H = 131072
    int hh = i & 63, n = (i >> 6) & 63, b = i >> 12;
    const float* p = d_h[0] + ((size_t)(b * T_) * NB + n) * H_ + hh;
    float s = 0.f;
    for (int t = 0; t < T_; t++) s += p[(size_t)t * NB * H_];
    d_gt[i] = s * (1.0f / T_);
}
__global__ void k_mean_n() {   // g_s[b,t,h] = mean_n h0
    int i = blockIdx.x * 256 + threadIdx.x;   // BT*H = 129024
    int hh = i & 63, bt = i >> 6;
    const float* p = d_h[0] + (size_t)bt * NB * H_ + hh;
    float s = 0.f;
    for (int n = 0; n < NB; n++) s += p[n * H_];
    d_gs[i] = s * (1.0f / NB);
}

// ---------------- small 9-gate gemms: out[g,m,:] = X[m,:] @ W[g or zs_idx[g]] ----
__global__ __launch_bounds__(256) void k_ninegemm(int which, const float* __restrict__ Wbase) {
    const int g = blockIdx.x;
    const int m0 = blockIdx.y * 64;
    const float* X = which ? d_gs : d_gt;
    float* out = which ? d_gst : d_gtt;
    const int M = which ? BT : (B_ * NB);
    const float* Wg = Wbase + (size_t)(which ? c_zs[g] : g) * 4096;

    __shared__ float XT[64][68];
    __shared__ float Wsm[64][68];
    const int tid = threadIdx.x;
    for (int i = tid; i < 4096; i += 256) {
        int r = i >> 6, k = i & 63;
        XT[k][r] = (m0 + r < M) ? X[(size_t)(m0 + r) * 64 + k] : 0.f;
        Wsm[r][k] = Wg[i];          // Wsm[in][out]
    }
    __syncthreads();
    const int tx = tid & 15, ty = tid >> 4;
    float acc[4][4];
    #pragma unroll
    for (int i = 0; i < 4; i++)
        #pragma unroll
        for (int j = 0; j < 4; j++) acc[i][j] = 0.f;
    #pragma unroll 16
    for (int kk = 0; kk < 64; kk++) {
        float4 a = *(const float4*)&XT[kk][ty * 4];
        float4 w = *(const float4*)&Wsm[kk][tx * 4];
        float av[4] = {a.x, a.y, a.z, a.w};
        float wv[4] = {w.x, w.y, w.z, w.w};
        #pragma unroll
        for (int i = 0; i < 4; i++)
            #pragma unroll
            for (int j = 0; j < 4; j++)
                acc[i][j] = fmaf(av[i], wv[j], acc[i][j]);
    }
    #pragma unroll
    for (int i = 0; i < 4; i++) {
        int row = m0 + ty * 4 + i;
        if (row >= M) break;
        float4 v = make_float4(acc[i][0], acc[i][1], acc[i][2], acc[i][3]);
        *(float4*)&out[((size_t)g * M + row) * 64 + tx * 4] = v;
    }
}

// ---------------- CONST[r, g*64+h] = h0[r,:]@U[g] + gtt + gst + bias ----------------
__global__ __launch_bounds__(256) void k_const(const float* __restrict__ U,
                                               const float* __restrict__ bb) {
    const int g = blockIdx.x;
    const int bt = blockIdx.y;          // 0..2015 -> rows bt*64..+63 share (b,t)
    const int b = bt / T_;
    __shared__ float XT[64][68];
    __shared__ float Us[64][68];
    const int tid = threadIdx.x;
    const int base = bt * 64;
    for (int i = tid; i < 4096; i += 256) {
        int n = i >> 6, k = i & 63;
        XT[k][n] = d_h[0][(size_t)(base + n) * 64 + k];
        Us[n][k] = U[(size_t)g * 4096 + i];   // Us[in][out]
    }
    __syncthreads();
    const int tx = tid & 15, ty = tid >> 4;
    float acc[4][4];
    #pragma unroll
    for (int i = 0; i < 4; i++)
        #pragma unroll
        for (int j = 0; j < 4; j++) acc[i][j] = 0.f;
    #pragma unroll 16
    for (int kk = 0; kk < 64; kk++) {
        float4 a = *(const float4*)&XT[kk][ty * 4];
        float4 w = *(const float4*)&Us[kk][tx * 4];
        float av[4] = {a.x, a.y, a.z, a.w};
        float wv[4] = {w.x, w.y, w.z, w.w};
        #pragma unroll
        for (int i = 0; i < 4; i++)
            #pragma unroll
            for (int j = 0; j < 4; j++)
                acc[i][j] = fmaf(av[i], wv[j], acc[i][j]);
    }
    #pragma unroll
    for (int i = 0; i < 4; i++) {
        int n = ty * 4 + i;
        int row = base + n;
        float4 agt = *(const float4*)&d_gtt[((size_t)g * B_ * NB + (b * NB + n)) * H_ + tx * 4];
        float4 ags = *(const float4*)&d_gst[((size_t)g * BT + bt) * H_ + tx * 4];
        float4 abb = *(const float4*)&bb[(size_t)g * H_ * H_ + n * H_ + tx * 4];
        float4 v;
        v.x = acc[i][0] + agt.x + ags.x + abb.x;
        v.y = acc[i][1] + agt.y + ags.y + abb.y;
        v.z = acc[i][2] + agt.z + ags.z + abb.z;
        v.w = acc[i][3] + agt.w + ags.w + abb.w;
        *(float4*)&d_cst[(size_t)row * NCOLS + g * 64 + tx * 4] = v;
    }
}

// ---------------- gather xin = [h(t-1), h, h(t+1), h(n-1)] ----------------
__global__ void k_gather(int cur) {
    int i = blockIdx.x * 256 + threadIdx.x;   // MROWS * 64 float4s
    int r = i >> 6;
    int c4 = (i & 63) << 2;                   // 0..252
    int n = r & 63, bt = r >> 6, t = bt % T_;
    int sec = c4 >> 6, hh = c4 & 63;
    const float* h = d_h[cur];
    float4 v = make_float4(0.f, 0.f, 0.f, 0.f);
    if (sec == 1) {
        v = *(const float4*)&h[(size_t)r * 64 + hh];
    } else if (sec == 0) {
        if (t > 0) v = *(const float4*)&h[(size_t)(r - 64) * 64 + hh];
    } else if (sec == 2) {
        if (t < T_ - 1) v = *(const float4*)&h[(size_t)(r + 64) * 64 + hh];
    } else {
        if (n > 0) v = *(const float4*)&h[(size_t)(r - 1) * 64 + hh];
    }
    *(float4*)&d_x[(size_t)r * KST + c4] = v;
}

// ---------------- step GEMM: PRE = CONST + Xin @ Wcat ----------------
// grid(9 gates, 1008 row-tiles); tile 128x64, K=256
__global__ __launch_bounds__(256) void k_stepgemm() {
    const int g = blockIdx.x;
    const int row0 = blockIdx.y * 128;
    const int gcol = g * 64;
    __shared__ float As[16][132];
    __shared__ float Bs[16][64];
    const int tid = threadIdx.x;
    const int tx = tid & 15, ty = tid >> 4;
    const int ar = tid >> 2, ac = (tid & 3) * 4;
    const int br = tid >> 4, bc = (tid & 15) * 4;
    float acc[8][4];
    #pragma unroll
    for (int i = 0; i < 8; i++)
        #pragma unroll
        for (int j = 0; j < 4; j++) acc[i][j] = 0.f;

    for (int k0 = 0; k0 < KST; k0 += 16) {
        float4 a0 = *(const float4*)&d_x[(size_t)(row0 + ar) * KST + k0 + ac];
        float4 a1 = *(const float4*)&d_x[(size_t)(row0 + ar + 64) * KST + k0 + ac];
        float4 b0 = *(const float4*)&d_wc[(size_t)(k0 + br) * NCOLS + gcol + bc];
        __syncthreads();
        As[ac + 0][ar] = a0.x; As[ac + 1][ar] = a0.y;
        As[ac + 2][ar] = a0.z; As[ac + 3][ar] = a0.w;
        As[ac + 0][ar + 64] = a1.x; As[ac + 1][ar + 64] = a1.y;
        As[ac + 2][ar + 64] = a1.z; As[ac + 3][ar + 64] = a1.w;
        *(float4*)&Bs[br][bc] = b0;
        __syncthreads();
        #pragma unroll
        for (int kk = 0; kk < 16; kk++) {
            float4 x0 = *(const float4*)&As[kk][ty * 8];
            float4 x1 = *(const float4*)&As[kk][ty * 8 + 4];
            float4 y  = *(const float4*)&Bs[kk][tx * 4];
            float a[8] = {x0.x, x0.y, x0.z, x0.w, x1.x, x1.y, x1.z, x1.w};
            float w[4] = {y.x, y.y, y.z, y.w};
            #pragma unroll
            for (int i = 0; i < 8; i++)
                #pragma unroll
                for (int j = 0; j < 4; j++)
                    acc[i][j] = fmaf(a[i], w[j], acc[i][j]);
        }
    }
    #pragma unroll
    for (int i = 0; i < 8; i++) {
        int row = row0 + ty * 8 + i;
        size_t o = (size_t)row * NCOLS + gcol + tx * 4;
        float4 cc = *(const float4*)&d_cst[o];
        float4 v = make_float4(acc[i][0] + cc.x, acc[i][1] + cc.y,
                               acc[i][2] + cc.z, acc[i][3] + cc.w);
        *(float4*)&d_pre[o] = v;
    }
}

// ---------------- cell update ----------------
__global__ void k_cell(int cur, float* __restrict__ hout) {
    int i = blockIdx.x * 256 + threadIdx.x;   // MROWS*H = 8257536
    int hh = i & 63;
    int r = i >> 6;
    int n = r & 63, bt = r >> 6;
    int t = bt % T_, b = bt / T_;
    const float* p = d_pre + (size_t)r * NCOLS + hh;
    float i_n  = sigm(p[0]);
    float f_lt = sigm(p[64]);
    float f_ft = sigm(p[128]);
    float f_rt = sigm(p[192]);
    float f_s  = sigm(p[256]);
    float f_gt = sigm(p[320]);
    float f_gs = sigm(p[384]);
    float o_n  = sigm(p[448]);
    float c_n  = tanhf(p[512]);
    const float* c_old = d_c[cur];
    float cc  = c_old[i];
    float ctb = (t > 0)      ? c_old[i - 4096] : 0.f;   // t-1 -> row r-64
    float cta = (t < T_ - 1) ? c_old[i + 4096] : 0.f;   // t+1
    float csb = (n > 0)      ? c_old[i - 64]   : 0.f;   // n-1
    float cgt = d_gt[(b * NB + n) * H_ + hh];
    float cgs = d_gs[bt * H_ + hh];
    float c = f_lt * ctb + f_ft * cc + f_rt * cta + f_s * csb
            + f_gt * cgt + f_gs * cgs + c_n * i_n;
    d_c[cur ^ 1][i] = c;
    float hv = o_n * tanhf(c);
    if (hout) hout[i] = hv;
    else      d_h[cur ^ 1][i] = hv;
}

extern "C" void kernel_launch(void* const* d_in, const int* in_sizes, int n_in,
                              void* d_out, int out_size) {
    const float* enc = (const float*)d_in[0];
    // d_in[1] = decoder_inputs: unused by the reference
    const float* Win = (const float*)d_in[2];
    const float* bin = (const float*)d_in[3];
    const float* U   = (const float*)d_in[4];
    const float* Wt  = (const float*)d_in[5];
    const float* Ws  = (const float*)d_in[6];
    const float* Zt  = (const float*)d_in[7];
    const float* Zs  = (const float*)d_in[8];
    const float* bb  = (const float*)d_in[9];
    float* out = (float*)d_out;

    k_wcat<<<(KST * NCOLS + 255) / 256, 256>>>(Wt, Ws);
    k_gemm_in<<<dim3(32, 16), 256>>>(enc, Win, bin);
    k_mean_t<<<(B_ * NB * H_) / 256, 256>>>();
    k_mean_n<<<(BT * H_) / 256, 256>>>();
    k_ninegemm<<<dim3(NG, 32), 256>>>(0, Zt);   // gtt: M=2048
    k_ninegemm<<<dim3(NG, 32), 256>>>(1, Zs);   // gst: M=2016
    k_const<<<dim3(NG, BT), 256>>>(U, bb);

    for (int s = 0; s < 3; s++) {
        int cur = s & 1;
        k_gather<<<(MROWS * 64) / 256, 256>>>(cur);
        k_stepgemm<<<dim3(NG, MROWS / 128), 256>>>();
        k_cell<<<(MROWS * H_) / 256, 256>>>(cur, (s == 2) ? out : nullptr);
    }
}

// round 5
// speedup vs baseline: 1.6010x; 1.0520x over previous
#include <cuda_runtime.h>
#include <math.h>

#define B_ 32
#define T_ 63
#define NB 64
#define H_ 64
#define KIN 4096
#define BT (B_*T_)            // 2016
#define MROWS (BT*NB)         // 129024
#define NG 9
#define NCOLS (NG*H_)         // 576
#define KST 256

// ---- scratch (static device allocations; no runtime allocs) ----
__device__ float d_h[2][MROWS*H_];          // 2 x 33 MB
__device__ float d_c[2][MROWS*H_];          // 2 x 33 MB
__device__ float d_cst[(size_t)MROWS*NCOLS]; // 297 MB: folded constants per (row, gate, h)
__device__ float d_pre[(size_t)MROWS*NCOLS]; // 297 MB: gate pre-activations
__device__ float d_x[(size_t)MROWS*KST];     // 132 MB: gathered step input
__device__ float d_gt[B_*NB*H_];             // mean over T
__device__ float d_gs[BT*H_];                // mean over N
__device__ float d_gtt[NG*B_*NB*H_];         // g_t @ Zt
__device__ float d_gst[NG*BT*H_];            // g_s @ Zs[idx]
__device__ float d_wc[KST*NCOLS];            // [Wt;Ws] concatenated, (256 x 576)

__constant__ int c_zs[NG] = {0,1,1,3,4,5,6,7,8};

__device__ __forceinline__ float sigm(float x) { return 1.0f / (1.0f + expf(-x)); }

// ---------------- build Wcat (256 x 576): rows 0..191 = Wt[g], 192..255 = Ws[g] ----
__global__ void k_wcat(const float* __restrict__ Wt, const float* __restrict__ Ws) {
    int i = blockIdx.x * 256 + threadIdx.x;      // KST*NCOLS = 147456
    if (i >= KST * NCOLS) return;
    int k = i / NCOLS;
    int c = i % NCOLS;
    int g = c >> 6, h = c & 63;
    float v = (k < 192) ? Wt[(g * 192 + k) * 64 + h]
                        : Ws[(g * 64 + (k - 192)) * 64 + h];
    d_wc[i] = v;
}

// ---------------- input projection: h0 = enc @ Win + bias ----------------
// C[2016,4096] ; 128x128 tile, K-chunk 16, 256 threads, 8x8 per thread
__global__ __launch_bounds__(256) void k_gemm_in(const float* __restrict__ A,
                                                 const float* __restrict__ W,
                                                 const float* __restrict__ bias) {
    __shared__ float As[16][132];   // transposed A tile (pad to dodge store conflicts)
    __shared__ float Bs[16][128];
    const int tid = threadIdx.x;
    const int tx = tid & 15, ty = tid >> 4;
    const int row0 = blockIdx.y * 128, col0 = blockIdx.x * 128;
    const int ar = tid >> 2, ac = (tid & 3) * 4;
    const int br = tid >> 5, bc = (tid & 31) * 4;
    float acc[8][8];
    #pragma unroll
    for (int i = 0; i < 8; i++)
        #pragma unroll
        for (int j = 0; j < 8; j++) acc[i][j] = 0.f;

    for (int k0 = 0; k0 < KIN; k0 += 16) {
        float4 a0 = make_float4(0.f,0.f,0.f,0.f), a1 = a0;
        if (row0 + ar < BT)
            a0 = *(const float4*)&A[(size_t)(row0 + ar) * KIN + k0 + ac];
        if (row0 + ar + 64 < BT)
            a1 = *(const float4*)&A[(size_t)(row0 + ar + 64) * KIN + k0 + ac];
        float4 b0 = *(const float4*)&W[(size_t)(k0 + br) * KIN + col0 + bc];
        float4 b1 = *(const float4*)&W[(size_t)(k0 + br + 8) * KIN + col0 + bc];
        __syncthreads();
        As[ac + 0][ar] = a0.x; As[ac + 1][ar] = a0.y;
        As[ac + 2][ar] = a0.z; As[ac + 3][ar] = a0.w;
        As[ac + 0][ar + 64] = a1.x; As[ac + 1][ar + 64] = a1.y;
        As[ac + 2][ar + 64] = a1.z; As[ac + 3][ar + 64] = a1.w;
        *(float4*)&Bs[br][bc]     = b0;
        *(float4*)&Bs[br + 8][bc] = b1;
        __syncthreads();
        #pragma unroll
        for (int kk = 0; kk < 16; kk++) {
            float4 x0 = *(const float4*)&As[kk][ty * 8];
            float4 x1 = *(const float4*)&As[kk][ty * 8 + 4];
            float4 y0 = *(const float4*)&Bs[kk][tx * 8];
            float4 y1 = *(const float4*)&Bs[kk][tx * 8 + 4];
            float a[8] = {x0.x, x0.y, x0.z, x0.w, x1.x, x1.y, x1.z, x1.w};
            float w[8] = {y0.x, y0.y, y0.z, y0.w, y1.x, y1.y, y1.z, y1.w};
            #pragma unroll
            for (int i = 0; i < 8; i++)
                #pragma unroll
                for (int j = 0; j < 8; j++)
                    acc[i][j] = fmaf(a[i], w[j], acc[i][j]);
        }
    }
    #pragma unroll
    for (int i = 0; i < 8; i++) {
        int row = row0 + ty * 8 + i;
        if (row >= BT) break;
        #pragma unroll
        for (int j = 0; j < 8; j += 4) {
            int col = col0 + tx * 8 + j;
            float4 v;
            v.x = acc[i][j + 0] + bias[col + 0];
            v.y = acc[i][j + 1] + bias[col + 1];
            v.z = acc[i][j + 2] + bias[col + 2];
            v.w = acc[i][j + 3] + bias[col + 3];
            *(float4*)&d_h[0][(size_t)row * KIN + col] = v;
            *(float4*)&d_c[0][(size_t)row * KIN + col] = v;
        }
    }
}

// ---------------- means ----------------
__global__ void k_mean_t() {   // g_t[b,n,h] = mean_t h0
    int i = blockIdx.x * 256 + threadIdx.x;   // B*NB*H = 131072
    int hh = i & 63, n = (i >> 6) & 63, b = i >> 12;
    const float* p = d_h[0] + ((size_t)(b * T_) * NB + n) * H_ + hh;
    float s = 0.f;
    for (int t = 0; t < T_; t++) s += p[(size_t)t * NB * H_];
    d_gt[i] = s * (1.0f / T_);
}
__global__ void k_mean_n() {   // g_s[b,t,h] = mean_n h0
    int i = blockIdx.x * 256 + threadIdx.x;   // BT*H = 129024
    int hh = i & 63, bt = i >> 6;
    const float* p = d_h[0] + (size_t)bt * NB * H_ + hh;
    float s = 0.f;
    for (int n = 0; n < NB; n++) s += p[n * H_];
    d_gs[i] = s * (1.0f / NB);
}

// ---------------- small 9-gate gemms: out[g,m,:] = X[m,:] @ W[g or zs_idx[g]] ----
__global__ __launch_bounds__(256) void k_ninegemm(int which, const float* __restrict__ Wbase) {
    const int g = blockIdx.x;
    const int m0 = blockIdx.y * 64;
    const float* X = which ? d_gs : d_gt;
    float* out = which ? d_gst : d_gtt;
    const int M = which ? BT : (B_ * NB);
    const float* Wg = Wbase + (size_t)(which ? c_zs[g] : g) * 4096;

    __shared__ float XT[64][68];
    __shared__ float Wsm[64][68];
    const int tid = threadIdx.x;
    for (int i = tid; i < 4096; i += 256) {
        int r = i >> 6, k = i & 63;
        XT[k][r] = (m0 + r < M) ? X[(size_t)(m0 + r) * 64 + k] : 0.f;
        Wsm[r][k] = Wg[i];          // Wsm[in][out]
    }
    __syncthreads();
    const int tx = tid & 15, ty = tid >> 4;
    float acc[4][4];
    #pragma unroll
    for (int i = 0; i < 4; i++)
        #pragma unroll
        for (int j = 0; j < 4; j++) acc[i][j] = 0.f;
    #pragma unroll 16
    for (int kk = 0; kk < 64; kk++) {
        float4 a = *(const float4*)&XT[kk][ty * 4];
        float4 w = *(const float4*)&Wsm[kk][tx * 4];
        float av[4] = {a.x, a.y, a.z, a.w};
        float wv[4] = {w.x, w.y, w.z, w.w};
        #pragma unroll
        for (int i = 0; i < 4; i++)
            #pragma unroll
            for (int j = 0; j < 4; j++)
                acc[i][j] = fmaf(av[i], wv[j], acc[i][j]);
    }
    #pragma unroll
    for (int i = 0; i < 4; i++) {
        int row = m0 + ty * 4 + i;
        if (row >= M) break;
        float4 v = make_float4(acc[i][0], acc[i][1], acc[i][2], acc[i][3]);
        *(float4*)&out[((size_t)g * M + row) * 64 + tx * 4] = v;
    }
}

// ---------------- CONST[r, g*64+h] = h0[r,:]@U[g] + gtt + gst + bias ----------------
__global__ __launch_bounds__(256) void k_const(const float* __restrict__ U,
                                               const float* __restrict__ bb) {
    const int g = blockIdx.x;
    const int bt = blockIdx.y;          // 0..2015 -> rows bt*64..+63 share (b,t)
    const int b = bt / T_;
    __shared__ float XT[64][68];
    __shared__ float Us[64][68];
    const int tid = threadIdx.x;
    const int base = bt * 64;
    for (int i = tid; i < 4096; i += 256) {
        int n = i >> 6, k = i & 63;
        XT[k][n] = d_h[0][(size_t)(base + n) * 64 + k];
        Us[n][k] = U[(size_t)g * 4096 + i];   // Us[in][out]
    }
    __syncthreads();
    const int tx = tid & 15, ty = tid >> 4;
    float acc[4][4];
    #pragma unroll
    for (int i = 0; i < 4; i++)
        #pragma unroll
        for (int j = 0; j < 4; j++) acc[i][j] = 0.f;
    #pragma unroll 16
    for (int kk = 0; kk < 64; kk++) {
        float4 a = *(const float4*)&XT[kk][ty * 4];
        float4 w = *(const float4*)&Us[kk][tx * 4];
        float av[4] = {a.x, a.y, a.z, a.w};
        float wv[4] = {w.x, w.y, w.z, w.w};
        #pragma unroll
        for (int i = 0; i < 4; i++)
            #pragma unroll
            for (int j = 0; j < 4; j++)
                acc[i][j] = fmaf(av[i], wv[j], acc[i][j]);
    }
    #pragma unroll
    for (int i = 0; i < 4; i++) {
        int n = ty * 4 + i;
        int row = base + n;
        float4 agt = *(const float4*)&d_gtt[((size_t)g * B_ * NB + (b * NB + n)) * H_ + tx * 4];
        float4 ags = *(const float4*)&d_gst[((size_t)g * BT + bt) * H_ + tx * 4];
        float4 abb = *(const float4*)&bb[(size_t)g * H_ * H_ + n * H_ + tx * 4];
        float4 v;
        v.x = acc[i][0] + agt.x + ags.x + abb.x;
        v.y = acc[i][1] + agt.y + ags.y + abb.y;
        v.z = acc[i][2] + agt.z + ags.z + abb.z;
        v.w = acc[i][3] + agt.w + ags.w + abb.w;
        *(float4*)&d_cst[(size_t)row * NCOLS + g * 64 + tx * 4] = v;
    }
}

// ---------------- gather xin = [h(t-1), h, h(t+1), h(n-1)] ----------------
__global__ void k_gather(int cur) {
    int i = blockIdx.x * 256 + threadIdx.x;   // MROWS * 64 float4s
    int r = i >> 6;
    int c4 = (i & 63) << 2;                   // 0..252
    int n = r & 63, bt = r >> 6, t = bt % T_;
    int sec = c4 >> 6, hh = c4 & 63;
    const float* h = d_h[cur];
    float4 v = make_float4(0.f, 0.f, 0.f, 0.f);
    if (sec == 1) {
        v = *(const float4*)&h[(size_t)r * 64 + hh];
    } else if (sec == 0) {
        if (t > 0) v = *(const float4*)&h[(size_t)(r - 64) * 64 + hh];
    } else if (sec == 2) {
        if (t < T_ - 1) v = *(const float4*)&h[(size_t)(r + 64) * 64 + hh];
    } else {
        if (n > 0) v = *(const float4*)&h[(size_t)(r - 1) * 64 + hh];
    }
    *(float4*)&d_x[(size_t)r * KST + c4] = v;
}

// ---------------- step GEMM: PRE = CONST + Xin @ Wcat ----------------
// grid(9 gates, 1008 row-tiles); tile 128x64, K=256
__global__ __launch_bounds__(256) void k_stepgemm() {
    const int g = blockIdx.x;
    const int row0 = blockIdx.y * 128;
    const int gcol = g * 64;
    __shared__ float As[16][132];
    __shared__ float Bs[16][64];
    const int tid = threadIdx.x;
    const int tx = tid & 15, ty = tid >> 4;
    const int ar = tid >> 2, ac = (tid & 3) * 4;
    const int br = tid >> 4, bc = (tid & 15) * 4;
    float acc[8][4];
    #pragma unroll
    for (int i = 0; i < 8; i++)
        #pragma unroll
        for (int j = 0; j < 4; j++) acc[i][j] = 0.f;

    for (int k0 = 0; k0 < KST; k0 += 16) {
        float4 a0 = *(const float4*)&d_x[(size_t)(row0 + ar) * KST + k0 + ac];
        float4 a1 = *(const float4*)&d_x[(size_t)(row0 + ar + 64) * KST + k0 + ac];
        float4 b0 = *(const float4*)&d_wc[(size_t)(k0 + br) * NCOLS + gcol + bc];
        __syncthreads();
        As[ac + 0][ar] = a0.x; As[ac + 1][ar] = a0.y;
        As[ac + 2][ar] = a0.z; As[ac + 3][ar] = a0.w;
        As[ac + 0][ar + 64] = a1.x; As[ac + 1][ar + 64] = a1.y;
        As[ac + 2][ar + 64] = a1.z; As[ac + 3][ar + 64] = a1.w;
        *(float4*)&Bs[br][bc] = b0;
        __syncthreads();
        #pragma unroll
        for (int kk = 0; kk < 16; kk++) {
            float4 x0 = *(const float4*)&As[kk][ty * 8];
            float4 x1 = *(const float4*)&As[kk][ty * 8 + 4];
            float4 y  = *(const float4*)&Bs[kk][tx * 4];
            float a[8] = {x0.x, x0.y, x0.z, x0.w, x1.x, x1.y, x1.z, x1.w};
            float w[4] = {y.x, y.y, y.z, y.w};
            #pragma unroll
            for (int i = 0; i < 8; i++)
                #pragma unroll
                for (int j = 0; j < 4; j++)
                    acc[i][j] = fmaf(a[i], w[j], acc[i][j]);
        }
    }
    #pragma unroll
    for (int i = 0; i < 8; i++) {
        int row = row0 + ty * 8 + i;
        size_t o = (size_t)row * NCOLS + gcol + tx * 4;
        float4 cc = *(const float4*)&d_cst[o];
        float4 v = make_float4(acc[i][0] + cc.x, acc[i][1] + cc.y,
                               acc[i][2] + cc.z, acc[i][3] + cc.w);
        *(float4*)&d_pre[o] = v;
    }
}

// ---------------- cell update ----------------
__global__ void k_cell(int cur, float* __restrict__ hout) {
    int i = blockIdx.x * 256 + threadIdx.x;   // MROWS*H = 8257536
    int hh = i & 63;
    int r = i >> 6;
    int n = r & 63, bt = r >> 6;
    int t = bt % T_, b = bt / T_;
    const float* p = d_pre + (size_t)r * NCOLS + hh;
    float i_n  = sigm(p[0]);
    float f_lt = sigm(p[64]);
    float f_ft = sigm(p[128]);
    float f_rt = sigm(p[192]);
    float f_s  = sigm(p[256]);
    float f_gt = sigm(p[320]);
    float f_gs = sigm(p[384]);
    float o_n  = sigm(p[448]);
    float c_n  = tanhf(p[512]);
    const float* c_old = d_c[cur];
    float cc  = c_old[i];
    float ctb = (t > 0)      ? c_old[i - 4096] : 0.f;   // t-1 -> row r-64
    float cta = (t < T_ - 1) ? c_old[i + 4096] : 0.f;   // t+1
    float csb = (n > 0)      ? c_old[i - 64]   : 0.f;   // n-1
    float cgt = d_gt[(b * NB + n) * H_ + hh];
    float cgs = d_gs[bt * H_ + hh];
    float c = f_lt * ctb + f_ft * cc + f_rt * cta + f_s * csb
            + f_gt * cgt + f_gs * cgs + c_n * i_n;
    d_c[cur ^ 1][i] = c;
    float hv = o_n * tanhf(c);
    if (hout) hout[i] = hv;
    else      d_h[cur ^ 1][i] = hv;
}

extern "C" void kernel_launch(void* const* d_in, const int* in_sizes, int n_in,
                              void* d_out, int out_size) {
    const float* enc = (const float*)d_in[0];
    // d_in[1] = decoder_inputs: unused by the reference
    const float* Win = (const float*)d_in[2];
    const float* bin = (const float*)d_in[3];
    const float* U   = (const float*)d_in[4];
    const float* Wt  = (const float*)d_in[5];
    const float* Ws  = (const float*)d_in[6];
    const float* Zt  = (const float*)d_in[7];
    const float* Zs  = (const float*)d_in[8];
    const float* bb  = (const float*)d_in[9];
    float* out = (float*)d_out;

    k_wcat<<<(KST * NCOLS + 255) / 256, 256>>>(Wt, Ws);
    k_gemm_in<<<dim3(32, 16), 256>>>(enc, Win, bin);
    k_mean_t<<<(B_ * NB * H_) / 256, 256>>>();
    k_mean_n<<<(BT * H_) / 256, 256>>>();
    k_ninegemm<<<dim3(NG, 32), 256>>>(0, Zt);   // gtt: M=2048
    k_ninegemm<<<dim3(NG, 32), 256>>>(1, Zs);   // gst: M=2016
    k_const<<<dim3(NG, BT), 256>>>(U, bb);

    for (int s = 0; s < 3; s++) {
        int cur = s & 1;
        k_gather<<<(MROWS * 64) / 256, 256>>>(cur);
        k_stepgemm<<<dim3(NG, MROWS / 128), 256>>>();
        k_cell<<<(MROWS * H_) / 256, 256>>>(cur, (s == 2) ? out : nullptr);
    }
}

// round 6
// speedup vs baseline: 1.6041x; 1.0019x over previous
#include <cuda_runtime.h>
#include <math.h>

#define B_ 32
#define T_ 63
#define NB 64
#define H_ 64
#define KIN 4096
#define BT (B_*T_)            // 2016
#define MROWS (BT*NB)         // 129024
#define NG 9
#define NCOLS (NG*H_)         // 576
#define KST 256

// ---- scratch (static device allocations; no runtime allocs) ----
__device__ float d_h[2][MROWS*H_];          // 2 x 33 MB
__device__ float d_c[2][MROWS*H_];          // 2 x 33 MB
__device__ float d_cst[(size_t)MROWS*NCOLS]; // 297 MB: folded constants per (row, gate, h)
__device__ float d_pre[(size_t)MROWS*NCOLS]; // 297 MB: gate pre-activations
__device__ float d_x[(size_t)MROWS*KST];     // 132 MB: gathered step input
__device__ float d_gt[B_*NB*H_];             // mean over T
__device__ float d_gs[BT*H_];                // mean over N
__device__ float d_gtt[NG*B_*NB*H_];         // g_t @ Zt
__device__ float d_gst[NG*BT*H_];            // g_s @ Zs[idx]
__device__ float d_wc[KST*NCOLS];            // [Wt;Ws] concatenated, (256 x 576)

__constant__ int c_zs[NG] = {0,1,1,3,4,5,6,7,8};

__device__ __forceinline__ float sigm(float x) { return 1.0f / (1.0f + expf(-x)); }

// ---------------- build Wcat (256 x 576): rows 0..191 = Wt[g], 192..255 = Ws[g] ----
__global__ void k_wcat(const float* __restrict__ Wt, const float* __restrict__ Ws) {
    int i = blockIdx.x * 256 + threadIdx.x;      // KST*NCOLS = 147456
    if (i >= KST * NCOLS) return;
    int k = i / NCOLS;
    int c = i % NCOLS;
    int g = c >> 6, h = c & 63;
    float v = (k < 192) ? Wt[(g * 192 + k) * 64 + h]
                        : Ws[(g * 64 + (k - 192)) * 64 + h];
    d_wc[i] = v;
}

// ---------------- input projection: h0 = enc @ Win + bias ----------------
// C[2016,4096] ; 128x128 tile, K-chunk 16, 256 threads, 8x8 per thread
__global__ __launch_bounds__(256) void k_gemm_in(const float* __restrict__ A,
                                                 const float* __restrict__ W,
                                                 const float* __restrict__ bias) {
    __shared__ float As[16][132];   // transposed A tile (pad to dodge store conflicts)
    __shared__ float Bs[16][128];
    const int tid = threadIdx.x;
    const int tx = tid & 15, ty = tid >> 4;
    const int row0 = blockIdx.y * 128, col0 = blockIdx.x * 128;
    const int ar = tid >> 2, ac = (tid & 3) * 4;
    const int br = tid >> 5, bc = (tid & 31) * 4;
    float acc[8][8];
    #pragma unroll
    for (int i = 0; i < 8; i++)
        #pragma unroll
        for (int j = 0; j < 8; j++) acc[i][j] = 0.f;

    for (int k0 = 0; k0 < KIN; k0 += 16) {
        float4 a0 = make_float4(0.f,0.f,0.f,0.f), a1 = a0;
        if (row0 + ar < BT)
            a0 = *(const float4*)&A[(size_t)(row0 + ar) * KIN + k0 + ac];
        if (row0 + ar + 64 < BT)
            a1 = *(const float4*)&A[(size_t)(row0 + ar + 64) * KIN + k0 + ac];
        float4 b0 = *(const float4*)&W[(size_t)(k0 + br) * KIN + col0 + bc];
        float4 b1 = *(const float4*)&W[(size_t)(k0 + br + 8) * KIN + col0 + bc];
        __syncthreads();
        As[ac + 0][ar] = a0.x; As[ac + 1][ar] = a0.y;
        As[ac + 2][ar] = a0.z; As[ac + 3][ar] = a0.w;
        As[ac + 0][ar + 64] = a1.x; As[ac + 1][ar + 64] = a1.y;
        As[ac + 2][ar + 64] = a1.z; As[ac + 3][ar + 64] = a1.w;
        *(float4*)&Bs[br][bc]     = b0;
        *(float4*)&Bs[br + 8][bc] = b1;
        __syncthreads();
        #pragma unroll
        for (int kk = 0; kk < 16; kk++) {
            float4 x0 = *(const float4*)&As[kk][ty * 8];
            float4 x1 = *(const float4*)&As[kk][ty * 8 + 4];
            float4 y0 = *(const float4*)&Bs[kk][tx * 8];
            float4 y1 = *(const float4*)&Bs[kk][tx * 8 + 4];
            float a[8] = {x0.x, x0.y, x0.z, x0.w, x1.x, x1.y, x1.z, x1.w};
            float w[8] = {y0.x, y0.y, y0.z, y0.w, y1.x, y1.y, y1.z, y1.w};
            #pragma unroll
            for (int i = 0; i < 8; i++)
                #pragma unroll
                for (int j = 0; j < 8; j++)
                    acc[i][j] = fmaf(a[i], w[j], acc[i][j]);
        }
    }
    #pragma unroll
    for (int i = 0; i < 8; i++) {
        int row = row0 + ty * 8 + i;
        if (row >= BT) break;
        #pragma unroll
        for (int j = 0; j < 8; j += 4) {
            int col = col0 + tx * 8 + j;
            float4 v;
            v.x = acc[i][j + 0] + bias[col + 0];
            v.y = acc[i][j + 1] + bias[col + 1];
            v.z = acc[i][j + 2] + bias[col + 2];
            v.w = acc[i][j + 3] + bias[col + 3];
            *(float4*)&d_h[0][(size_t)row * KIN + col] = v;
            *(float4*)&d_c[0][(size_t)row * KIN + col] = v;
        }
    }
}

// ---------------- means ----------------
__global__ void k_mean_t() {   // g_t[b,n,h] = mean_t h0
    int i = blockIdx.x * 256 + threadIdx.x;   // B*NB*H = 131072
    int hh = i & 63, n = (i >> 6) & 63, b = i >> 12;
    const float* p = d_h[0] + ((size_t)(b * T_) * NB + n) * H_ + hh;
    float s = 0.f;
    for (int t = 0; t < T_; t++) s += p[(size_t)t * NB * H_];
    d_gt[i] = s * (1.0f / T_);
}
__global__ void k_mean_n() {   // g_s[b,t,h] = mean_n h0
    int i = blockIdx.x * 256 + threadIdx.x;   // BT*H = 129024
    int hh = i & 63, bt = i >> 6;
    const float* p = d_h[0] + (size_t)bt * NB * H_ + hh;
    float s = 0.f;
    for (int n = 0; n < NB; n++) s += p[n * H_];
    d_gs[i] = s * (1.0f / NB);
}

// ---------------- small 9-gate gemms: out[g,m,:] = X[m,:] @ W[g or zs_idx[g]] ----
__global__ __launch_bounds__(256) void k_ninegemm(int which, const float* __restrict__ Wbase) {
    const int g = blockIdx.x;
    const int m0 = blockIdx.y * 64;
    const float* X = which ? d_gs : d_gt;
    float* out = which ? d_gst : d_gtt;
    const int M = which ? BT : (B_ * NB);
    const float* Wg = Wbase + (size_t)(which ? c_zs[g] : g) * 4096;

    __shared__ float XT[64][68];
    __shared__ float Wsm[64][68];
    const int tid = threadIdx.x;
    for (int i = tid; i < 4096; i += 256) {
        int r = i >> 6, k = i & 63;
        XT[k][r] = (m0 + r < M) ? X[(size_t)(m0 + r) * 64 + k] : 0.f;
        Wsm[r][k] = Wg[i];          // Wsm[in][out]
    }
    __syncthreads();
    const int tx = tid & 15, ty = tid >> 4;
    float acc[4][4];
    #pragma unroll
    for (int i = 0; i < 4; i++)
        #pragma unroll
        for (int j = 0; j < 4; j++) acc[i][j] = 0.f;
    #pragma unroll 16
    for (int kk = 0; kk < 64; kk++) {
        float4 a = *(const float4*)&XT[kk][ty * 4];
        float4 w = *(const float4*)&Wsm[kk][tx * 4];
        float av[4] = {a.x, a.y, a.z, a.w};
        float wv[4] = {w.x, w.y, w.z, w.w};
        #pragma unroll
        for (int i = 0; i < 4; i++)
            #pragma unroll
            for (int j = 0; j < 4; j++)
                acc[i][j] = fmaf(av[i], wv[j], acc[i][j]);
    }
    #pragma unroll
    for (int i = 0; i < 4; i++) {
        int row = m0 + ty * 4 + i;
        if (row >= M) break;
        float4 v = make_float4(acc[i][0], acc[i][1], acc[i][2], acc[i][3]);
        *(float4*)&out[((size_t)g * M + row) * 64 + tx * 4] = v;
    }
}

// ---------------- CONST[r, g*64+h] = h0[r,:]@U[g] + gtt + gst + bias ----------------
__global__ __launch_bounds__(256) void k_const(const float* __restrict__ U,
                                               const float* __restrict__ bb) {
    const int g = blockIdx.x;
    const int bt = blockIdx.y;          // 0..2015 -> rows bt*64..+63 share (b,t)
    const int b = bt / T_;
    __shared__ float XT[64][68];
    __shared__ float Us[64][68];
    const int tid = threadIdx.x;
    const int base = bt * 64;
    for (int i = tid; i < 4096; i += 256) {
        int n = i >> 6, k = i & 63;
        XT[k][n] = d_h[0][(size_t)(base + n) * 64 + k];
        Us[n][k] = U[(size_t)g * 4096 + i];   // Us[in][out]
    }
    __syncthreads();
    const int tx = tid & 15, ty = tid >> 4;
    float acc[4][4];
    #pragma unroll
    for (int i = 0; i < 4; i++)
        #pragma unroll
        for (int j = 0; j < 4; j++) acc[i][j] = 0.f;
    #pragma unroll 16
    for (int kk = 0; kk < 64; kk++) {
        float4 a = *(const float4*)&XT[kk][ty * 4];
        float4 w = *(const float4*)&Us[kk][tx * 4];
        float av[4] = {a.x, a.y, a.z, a.w};
        float wv[4] = {w.x, w.y, w.z, w.w};
        #pragma unroll
        for (int i = 0; i < 4; i++)
            #pragma unroll
            for (int j = 0; j < 4; j++)
                acc[i][j] = fmaf(av[i], wv[j], acc[i][j]);
    }
    #pragma unroll
    for (int i = 0; i < 4; i++) {
        int n = ty * 4 + i;
        int row = base + n;
        float4 agt = *(const float4*)&d_gtt[((size_t)g * B_ * NB + (b * NB + n)) * H_ + tx * 4];
        float4 ags = *(const float4*)&d_gst[((size_t)g * BT + bt) * H_ + tx * 4];
        float4 abb = *(const float4*)&bb[(size_t)g * H_ * H_ + n * H_ + tx * 4];
        float4 v;
        v.x = acc[i][0] + agt.x + ags.x + abb.x;
        v.y = acc[i][1] + agt.y + ags.y + abb.y;
        v.z = acc[i][2] + agt.z + ags.z + abb.z;
        v.w = acc[i][3] + agt.w + ags.w + abb.w;
        *(float4*)&d_cst[(size_t)row * NCOLS + g * 64 + tx * 4] = v;
    }
}

// ---------------- gather xin = [h(t-1), h, h(t+1), h(n-1)] ----------------
__global__ void k_gather(int cur) {
    int i = blockIdx.x * 256 + threadIdx.x;   // MROWS * 64 float4s
    int r = i >> 6;
    int c4 = (i & 63) << 2;                   // 0..252
    int n = r & 63, bt = r >> 6, t = bt % T_;
    int sec = c4 >> 6, hh = c4 & 63;
    const float* h = d_h[cur];
    float4 v = make_float4(0.f, 0.f, 0.f, 0.f);
    if (sec == 1) {
        v = *(const float4*)&h[(size_t)r * 64 + hh];
    } else if (sec == 0) {
        if (t > 0) v = *(const float4*)&h[(size_t)(r - 64) * 64 + hh];
    } else if (sec == 2) {
        if (t < T_ - 1) v = *(const float4*)&h[(size_t)(r + 64) * 64 + hh];
    } else {
        if (n > 0) v = *(const float4*)&h[(size_t)(r - 1) * 64 + hh];
    }
    *(float4*)&d_x[(size_t)r * KST + c4] = v;
}

// ---------------- step GEMM: PRE = CONST + Xin @ Wcat ----------------
// grid(9 gates, 1008 row-tiles); tile 128x64, K=256
__global__ __launch_bounds__(256) void k_stepgemm() {
    const int g = blockIdx.x;
    const int row0 = blockIdx.y * 128;
    const int gcol = g * 64;
    __shared__ float As[16][132];
    __shared__ float Bs[16][64];
    const int tid = threadIdx.x;
    const int tx = tid & 15, ty = tid >> 4;
    const int ar = tid >> 2, ac = (tid & 3) * 4;
    const int br = tid >> 4, bc = (tid & 15) * 4;
    float acc[8][4];
    #pragma unroll
    for (int i = 0; i < 8; i++)
        #pragma unroll
        for (int j = 0; j < 4; j++) acc[i][j] = 0.f;

    for (int k0 = 0; k0 < KST; k0 += 16) {
        float4 a0 = *(const float4*)&d_x[(size_t)(row0 + ar) * KST + k0 + ac];
        float4 a1 = *(const float4*)&d_x[(size_t)(row0 + ar + 64) * KST + k0 + ac];
        float4 b0 = *(const float4*)&d_wc[(size_t)(k0 + br) * NCOLS + gcol + bc];
        __syncthreads();
        As[ac + 0][ar] = a0.x; As[ac + 1][ar] = a0.y;
        As[ac + 2][ar] = a0.z; As[ac + 3][ar] = a0.w;
        As[ac + 0][ar + 64] = a1.x; As[ac + 1][ar + 64] = a1.y;
        As[ac + 2][ar + 64] = a1.z; As[ac + 3][ar + 64] = a1.w;
        *(float4*)&Bs[br][bc] = b0;
        __syncthreads();
        #pragma unroll
        for (int kk = 0; kk < 16; kk++) {
            float4 x0 = *(const float4*)&As[kk][ty * 8];
            float4 x1 = *(const float4*)&As[kk][ty * 8 + 4];
            float4 y  = *(const float4*)&Bs[kk][tx * 4];
            float a[8] = {x0.x, x0.y, x0.z, x0.w, x1.x, x1.y, x1.z, x1.w};
            float w[4] = {y.x, y.y, y.z, y.w};
            #pragma unroll
            for (int i = 0; i < 8; i++)
                #pragma unroll
                for (int j = 0; j < 4; j++)
                    acc[i][j] = fmaf(a[i], w[j], acc[i][j]);
        }
    }
    #pragma unroll
    for (int i = 0; i < 8; i++) {
        int row = row0 + ty * 8 + i;
        size_t o = (size_t)row * NCOLS + gcol + tx * 4;
        float4 cc = *(const float4*)&d_cst[o];
        float4 v = make_float4(acc[i][0] + cc.x, acc[i][1] + cc.y,
                               acc[i][2] + cc.z, acc[i][3] + cc.w);
        *(float4*)&d_pre[o] = v;
    }
}

// ---------------- cell update ----------------
__global__ void k_cell(int cur, float* __restrict__ hout) {
    int i = blockIdx.x * 256 + threadIdx.x;   // MROWS*H = 8257536
    int hh = i & 63;
    int r = i >> 6;
    int n = r & 63, bt = r >> 6;
    int t = bt % T_, b = bt / T_;
    const float* p = d_pre + (size_t)r * NCOLS + hh;
    float i_n  = sigm(p[0]);
    float f_lt = sigm(p[64]);
    float f_ft = sigm(p[128]);
    float f_rt = sigm(p[192]);
    float f_s  = sigm(p[256]);
    float f_gt = sigm(p[320]);
    float f_gs = sigm(p[384]);
    float o_n  = sigm(p[448]);
    float c_n  = tanhf(p[512]);
    const float* c_old = d_c[cur];
    float cc  = c_old[i];
    float ctb = (t > 0)      ? c_old[i - 4096] : 0.f;   // t-1 -> row r-64
    float cta = (t < T_ - 1) ? c_old[i + 4096] : 0.f;   // t+1
    float csb = (n > 0)      ? c_old[i - 64]   : 0.f;   // n-1
    float cgt = d_gt[(b * NB + n) * H_ + hh];
    float cgs = d_gs[bt * H_ + hh];
    float c = f_lt * ctb + f_ft * cc + f_rt * cta + f_s * csb
            + f_gt * cgt + f_gs * cgs + c_n * i_n;
    d_c[cur ^ 1][i] = c;
    float hv = o_n * tanhf(c);
    if (hout) hout[i] = hv;
    else      d_h[cur ^ 1][i] = hv;
}

extern "C" void kernel_launch(void* const* d_in, const int* in_sizes, int n_in,
                              void* d_out, int out_size) {
    const float* enc = (const float*)d_in[0];
    // d_in[1] = decoder_inputs: unused by the reference
    const float* Win = (const float*)d_in[2];
    const float* bin = (const float*)d_in[3];
    const float* U   = (const float*)d_in[4];
    const float* Wt  = (const float*)d_in[5];
    const float* Ws  = (const float*)d_in[6];
    const float* Zt  = (const float*)d_in[7];
    const float* Zs  = (const float*)d_in[8];
    const float* bb  = (const float*)d_in[9];
    float* out = (float*)d_out;

    k_wcat<<<(KST * NCOLS + 255) / 256, 256>>>(Wt, Ws);
    k_gemm_in<<<dim3(32, 16), 256>>>(enc, Win, bin);
    k_mean_t<<<(B_ * NB * H_) / 256, 256>>>();
    k_mean_n<<<(BT * H_) / 256, 256>>>();
    k_ninegemm<<<dim3(NG, 32), 256>>>(0, Zt);   // gtt: M=2048
    k_ninegemm<<<dim3(NG, 32), 256>>>(1, Zs);   // gst: M=2016
    k_const<<<dim3(NG, BT), 256>>>(U, bb);

    for (int s = 0; s < 3; s++) {
        int cur = s & 1;
        k_gather<<<(MROWS * 64) / 256, 256>>>(cur);
        k_stepgemm<<<dim3(NG, MROWS / 128), 256>>>();
        k_cell<<<(MROWS * H_) / 256, 256>>>(cur, (s == 2) ? out : nullptr);
    }
}